// round 5
// baseline (speedup 1.0000x reference)
#include <cuda_runtime.h>

// VTBPR fused kernel (R5): persistent-ish, 8 rows per CTA.
//   score[b] = item_beta[i] + user_beta[u] + <ug,ig> + <tv,vf_b> + <tt,tf_b>
//   metapath[b,0,p,l,:] = ug if path_type==0, ig if ==1, else 0
//
// d_out = [ score (B floats) | metapath (B*16*512 floats) ]
//
// R5 vs R2 (59.9us best): grid 8192 -> 1024 CTAs (single wave, no wave
// transitions), 8 rows per CTA, all path_types staged once, NO barriers
// inside the row loop, 256KB contiguous writes per CTA.

#define HIDDEN 512
#define VEC    (HIDDEN / 4)   // 128 float4 lanes per vector
#define PL     16             // P*L
#define RPC    8              // rows per CTA

__global__ void __launch_bounds__(VEC)
vtbpr_kernel(const float* __restrict__ user_gama,
             const float* __restrict__ item_gama,
             const float* __restrict__ user_beta,
             const float* __restrict__ item_beta,
             const float* __restrict__ theta_user_visual,
             const float* __restrict__ theta_user_text,
             const float* __restrict__ visual_features,
             const float* __restrict__ textural_features,
             const int*   __restrict__ user_idx,
             const int*   __restrict__ item_idx,
             const int*   __restrict__ path_type,
             float* __restrict__ out,
             int B)
{
    const int tid  = threadIdx.x;          // 0..127
    const int wid  = tid >> 5;             // warp 0..3
    const int row0 = blockIdx.x * RPC;

    __shared__ int   pt_all[RPC * PL];     // 128 ints
    __shared__ float wsum[RPC][4];

    // Stage all 8 rows' path types with one load+STS, one barrier.
    if (row0 + (tid >> 4) < B)
        pt_all[tid] = __ldg(&path_type[(size_t)row0 * PL + tid]);
    __syncthreads();

    #pragma unroll 1
    for (int r = 0; r < RPC; r++) {
        const int b = row0 + r;
        if (b >= B) break;

        const int u = __ldg(&user_idx[b]);
        const int i = __ldg(&item_idx[b]);

        const float4* ug_p = (const float4*)(user_gama         + (size_t)u * HIDDEN);
        const float4* ig_p = (const float4*)(item_gama         + (size_t)i * HIDDEN);
        const float4* tv_p = (const float4*)(theta_user_visual + (size_t)u * HIDDEN);
        const float4* tt_p = (const float4*)(theta_user_text   + (size_t)u * HIDDEN);
        const float4* vf_p = (const float4*)(visual_features   + (size_t)b * HIDDEN);
        const float4* tf_p = (const float4*)(textural_features + (size_t)b * HIDDEN);

        const float4 ug4 = __ldg(&ug_p[tid]);
        const float4 ig4 = __ldg(&ig_p[tid]);
        const float4 tv4 = __ldg(&tv_p[tid]);
        const float4 tt4 = __ldg(&tt_p[tid]);
        const float4 vf4 = __ldg(&vf_p[tid]);
        const float4 tf4 = __ldg(&tf_p[tid]);

        // Metapath scatter: 16 coalesced STG.128 per thread, fire-and-forget.
        float4* mp = (float4*)(out + B + (size_t)b * PL * HIDDEN);
        const float4 zero4 = make_float4(0.f, 0.f, 0.f, 0.f);
        const int* ptr = &pt_all[r * PL];

        #pragma unroll
        for (int j = 0; j < PL; j++) {
            const int t = ptr[j];                       // smem broadcast
            const float4 v = (t == 0) ? ug4 : ((t == 1) ? ig4 : zero4);
            mp[(size_t)j * VEC + tid] = v;
        }

        // Dot products + warp reduce; each warp owns its wsum slot -> no barrier.
        float partial =
            ug4.x * ig4.x + ug4.y * ig4.y + ug4.z * ig4.z + ug4.w * ig4.w +
            tv4.x * vf4.x + tv4.y * vf4.y + tv4.z * vf4.z + tv4.w * vf4.w +
            tt4.x * tf4.x + tt4.y * tf4.y + tt4.z * tf4.z + tt4.w * tf4.w;

        #pragma unroll
        for (int off = 16; off > 0; off >>= 1)
            partial += __shfl_xor_sync(0xFFFFFFFFu, partial, off);

        if ((tid & 31) == 0) wsum[r][wid] = partial;
    }

    __syncthreads();

    // Emit the 8 scores.
    if (tid < RPC) {
        const int b = row0 + tid;
        if (b < B) {
            const int u = __ldg(&user_idx[b]);
            const int i = __ldg(&item_idx[b]);
            float s = __ldg(&user_beta[u]) + __ldg(&item_beta[i]);
            s += wsum[tid][0] + wsum[tid][1] + wsum[tid][2] + wsum[tid][3];
            out[b] = s;
        }
    }
}

extern "C" void kernel_launch(void* const* d_in, const int* in_sizes, int n_in,
                              void* d_out, int out_size)
{
    const float* user_gama          = (const float*)d_in[0];
    const float* item_gama          = (const float*)d_in[1];
    const float* user_beta          = (const float*)d_in[2];
    const float* item_beta          = (const float*)d_in[3];
    const float* theta_user_visual  = (const float*)d_in[4];
    const float* theta_user_text    = (const float*)d_in[5];
    const float* visual_features    = (const float*)d_in[6];
    const float* textural_features  = (const float*)d_in[7];
    const int*   user_idx           = (const int*)d_in[8];
    const int*   item_idx           = (const int*)d_in[9];
    const int*   path_type          = (const int*)d_in[10];

    const int B = in_sizes[8];                 // 8192
    const int grid = (B + RPC - 1) / RPC;      // 1024

    vtbpr_kernel<<<grid, VEC>>>(user_gama, item_gama, user_beta, item_beta,
                                theta_user_visual, theta_user_text,
                                visual_features, textural_features,
                                user_idx, item_idx, path_type,
                                (float*)d_out, B);
}

// round 6
// speedup vs baseline: 1.1523x; 1.1523x over previous
#include <cuda_runtime.h>

// VTBPR fused kernel (R6): R2 structure, register-minimized for occupancy.
//   score[b] = item_beta[i] + user_beta[u] + <ug,ig> + <tv,vf_b> + <tt,tf_b>
//   metapath[b,0,p,l,:] = ug if path_type==0, ig if ==1, else 0
//
// d_out = [ score (B floats) | metapath (B*16*512 floats) ]
//
// R6 vs R2 (59.9us, 40 regs, occ 67.9% == register-limited 48-warp cap):
//  - phased loads: (ug,ig -> stores + dot) then (tv,vf -> dot) then
//    (tt,tf -> dot). Peak live float4 count drops 6 -> 2-3.
//  - __launch_bounds__(128, 16) caps regs at 32 -> 64-warp occupancy
//    ceiling, +33% resident warps -> deeper chip-wide store queue.

#define HIDDEN 512
#define VEC    (HIDDEN / 4)   // 128 float4 lanes
#define PL     16             // P*L

__global__ void __launch_bounds__(VEC, 16)
vtbpr_kernel(const float* __restrict__ user_gama,
             const float* __restrict__ item_gama,
             const float* __restrict__ user_beta,
             const float* __restrict__ item_beta,
             const float* __restrict__ theta_user_visual,
             const float* __restrict__ theta_user_text,
             const float* __restrict__ visual_features,
             const float* __restrict__ textural_features,
             const int*   __restrict__ user_idx,
             const int*   __restrict__ item_idx,
             const int*   __restrict__ path_type,
             float* __restrict__ out,
             int B)
{
    const int b   = blockIdx.x;
    const int tid = threadIdx.x;           // 0..127

    __shared__ int   pt[PL];
    __shared__ float wsum[VEC / 32];

    const int u = user_idx[b];
    const int i = item_idx[b];

    if (tid < PL) pt[tid] = path_type[b * PL + tid];

    // ---- Phase 1: ug/ig -> metapath scatter + first dot ----
    const float4 ug4 = ((const float4*)(user_gama + (size_t)u * HIDDEN))[tid];
    const float4 ig4 = ((const float4*)(item_gama + (size_t)i * HIDDEN))[tid];

    __syncthreads();   // orders pt STS; arrives with ug/ig LDGs in flight

    float4* mp = (float4*)(out + B + (size_t)b * PL * HIDDEN);
    const float4 zero4 = make_float4(0.f, 0.f, 0.f, 0.f);

    #pragma unroll
    for (int j = 0; j < PL; j++) {
        const int t = pt[j];
        const float4 v = (t == 0) ? ug4 : ((t == 1) ? ig4 : zero4);
        mp[(size_t)j * VEC + tid] = v;
    }

    float partial =
        ug4.x * ig4.x + ug4.y * ig4.y + ug4.z * ig4.z + ug4.w * ig4.w;

    // ---- Phase 2: tv/vf dot (ug/ig registers now dead) ----
    {
        const float4 tv4 = ((const float4*)(theta_user_visual + (size_t)u * HIDDEN))[tid];
        const float4 vf4 = ((const float4*)(visual_features   + (size_t)b * HIDDEN))[tid];
        partial += tv4.x * vf4.x + tv4.y * vf4.y + tv4.z * vf4.z + tv4.w * vf4.w;
    }

    // ---- Phase 3: tt/tf dot ----
    {
        const float4 tt4 = ((const float4*)(theta_user_text     + (size_t)u * HIDDEN))[tid];
        const float4 tf4 = ((const float4*)(textural_features   + (size_t)b * HIDDEN))[tid];
        partial += tt4.x * tf4.x + tt4.y * tf4.y + tt4.z * tf4.z + tt4.w * tf4.w;
    }

    // ---- Reduce + epilogue ----
    #pragma unroll
    for (int off = 16; off > 0; off >>= 1)
        partial += __shfl_xor_sync(0xFFFFFFFFu, partial, off);

    if ((tid & 31) == 0) wsum[tid >> 5] = partial;
    __syncthreads();

    if (tid == 0) {
        float s = user_beta[u] + item_beta[i];
        #pragma unroll
        for (int w = 0; w < VEC / 32; w++) s += wsum[w];
        out[b] = s;
    }
}

extern "C" void kernel_launch(void* const* d_in, const int* in_sizes, int n_in,
                              void* d_out, int out_size)
{
    const float* user_gama          = (const float*)d_in[0];
    const float* item_gama          = (const float*)d_in[1];
    const float* user_beta          = (const float*)d_in[2];
    const float* item_beta          = (const float*)d_in[3];
    const float* theta_user_visual  = (const float*)d_in[4];
    const float* theta_user_text    = (const float*)d_in[5];
    const float* visual_features    = (const float*)d_in[6];
    const float* textural_features  = (const float*)d_in[7];
    const int*   user_idx           = (const int*)d_in[8];
    const int*   item_idx           = (const int*)d_in[9];
    const int*   path_type          = (const int*)d_in[10];

    const int B = in_sizes[8];  // 8192

    vtbpr_kernel<<<B, VEC>>>(user_gama, item_gama, user_beta, item_beta,
                             theta_user_visual, theta_user_text,
                             visual_features, textural_features,
                             user_idx, item_idx, path_type,
                             (float*)d_out, B);
}